// round 2
// baseline (speedup 1.0000x reference)
#include <cuda_runtime.h>
#include <cstdint>
#include <cstddef>

#define BATCH 128
#define TT 512
#define NFEAT 508
#define NCMD 4
#define IN0 512
#define H0 152
#define H1 101
#define H2 3
#define G0 456
#define G1P 304
#define G2P 12
#define D1 253
#define D2 104
#define SW0X 512
#define SU0 456
#define KC0 110

// ---------------- device scratch (static, allowed) ----------------
__device__ float g_W0xT[IN0 * SW0X];            // [512][512] input-part weights, [k][n]
__device__ float g_W0hT[H0 * SU0];              // [152][456] recurrent L0, [k][n]
__device__ float g_W1T[D1 * G1P];               // [253][304]
__device__ float g_W2T[D2 * G2P];               // [104][12]
__device__ float g_b0c[SW0X];
__device__ float g_b1c[G1P];
__device__ float g_b2c[16];
__device__ float g_U0[(size_t)BATCH * TT * SU0];  // [65536][456]

// ---------------- fast activations (abs err ~1e-6) ----------------
__device__ __forceinline__ float tanh_f(float x) {
    float e = __expf(fminf(fmaxf(2.0f * x, -80.0f), 80.0f));
    return 1.0f - __fdividef(2.0f, 1.0f + e);
}
__device__ __forceinline__ float sig_f(float x) {
    float e = __expf(fminf(fmaxf(-x, -80.0f), 80.0f));
    return __fdividef(1.0f, 1.0f + e);
}

// ---------------- prep: masked/transposed/gate-combined weights ----------------
__global__ void prep_kernel(const float* __restrict__ l0W, const float* __restrict__ l0b,
                            const float* __restrict__ l1W, const float* __restrict__ l1b,
                            const float* __restrict__ l2W, const float* __restrict__ l2b,
                            const float* __restrict__ m0, const float* __restrict__ m1,
                            const float* __restrict__ m2) {
    const int R0 = IN0 * SW0X;              // 262144
    const int R1 = R0 + H0 * SU0;           // 331456
    const int R2 = R1 + D1 * G1P;           // 408368
    const int R3 = R2 + D2 * G2P;           // 409616
    const int R4 = R3 + SW0X;               // 410128
    const int R5 = R4 + G1P;                // 410432
    const int R6 = R5 + 16;                 // 410448
    int stride = gridDim.x * blockDim.x;
    for (int i = blockIdx.x * blockDim.x + threadIdx.x; i < R6; i += stride) {
        if (i < R0) {
            int k = i / SW0X, n = i % SW0X;
            float v = 0.0f;
            if (n < G0) {
                int g = n / H0, j = n % H0;
                if (g < 2) v = l0W[(g * H0 + j) * 664 + k] * m0[j * 664 + k];
                else       v = l0W[(2 * H0 + j) * 664 + k] + l0W[(3 * H0 + j) * 664 + k];
            }
            g_W0xT[i] = v;
        } else if (i < R1) {
            int i2 = i - R0, k = i2 / SU0, n = i2 % SU0;
            int g = n / H0, j = n % H0, col = IN0 + k;
            float v;
            if (g < 2) v = l0W[(g * H0 + j) * 664 + col] * m0[j * 664 + col];
            else       v = l0W[(2 * H0 + j) * 664 + col] + l0W[(3 * H0 + j) * 664 + col];
            g_W0hT[i2] = v;
        } else if (i < R2) {
            int i2 = i - R1, k = i2 / G1P, n = i2 % G1P;
            float v = 0.0f;
            if (n < 3 * H1) {
                int g = n / H1, j = n % H1;
                if (g < 2) v = l1W[(g * H1 + j) * D1 + k] * m1[j * D1 + k];
                else       v = l1W[(2 * H1 + j) * D1 + k] + l1W[(3 * H1 + j) * D1 + k];
            }
            g_W1T[i2] = v;
        } else if (i < R3) {
            int i2 = i - R2, k = i2 / G2P, n = i2 % G2P;
            float v = 0.0f;
            if (n < 3 * H2) {
                int g = n / H2, j = n % H2;
                if (g < 2) v = l2W[(g * H2 + j) * D2 + k] * m2[j * D2 + k];
                else       v = l2W[(2 * H2 + j) * D2 + k] + l2W[(3 * H2 + j) * D2 + k];
            }
            g_W2T[i2] = v;
        } else if (i < R4) {
            int n = i - R3;
            float v = 0.0f;
            if (n < G0) {
                int g = n / H0, j = n % H0;
                if (g < 2) v = l0b[g * H0 + j];
                else       v = l0b[2 * H0 + j] + l0b[3 * H0 + j];
            }
            g_b0c[n] = v;
        } else if (i < R5) {
            int n = i - R4;
            float v = 0.0f;
            if (n < 3 * H1) {
                int g = n / H1, j = n % H1;
                if (g < 2) v = l1b[g * H1 + j];
                else       v = l1b[2 * H1 + j] + l1b[3 * H1 + j];
            }
            g_b1c[n] = v;
        } else {
            int n = i - R5;
            float v = 0.0f;
            if (n < 3 * H2) {
                int g = n / H2, j = n % H2;
                if (g < 2) v = l2b[g * H2 + j];
                else       v = l2b[2 * H2 + j] + l2b[3 * H2 + j];
            }
            g_b2c[n] = v;
        }
    }
}

// ---------------- phase-1 GEMM: U0 = [feat|cmd] @ W0xT + b0c ----------------
// M=65536, K=512, N=456 (padded 512). 64x64x32 tiles, 256 threads, 4x4 micro.
__global__ void __launch_bounds__(256) gemm_u0(const float* __restrict__ feat,
                                               const float* __restrict__ cmd) {
    __shared__ float As[32][68];
    __shared__ float Bs[32][68];
    int tid = threadIdx.x;
    int tx = tid & 15, ty = tid >> 4;
    int m0 = blockIdx.y * 64, n0 = blockIdx.x * 64;

    float acc[4][4];
#pragma unroll
    for (int i = 0; i < 4; i++)
#pragma unroll
        for (int j = 0; j < 4; j++) acc[i][j] = 0.0f;

    for (int kc = 0; kc < IN0; kc += 32) {
#pragma unroll
        for (int it = 0; it < 2; it++) {
            int lin = tid * 2 + it;
            int row = lin >> 3;
            int kq = (lin & 7) << 2;
            int m = m0 + row, k = kc + kq;
            float4 v;
            if (k < NFEAT) v = *(const float4*)(feat + (size_t)m * NFEAT + k);
            else           v = *(const float4*)(cmd + (size_t)m * NCMD);
            As[kq + 0][row] = v.x; As[kq + 1][row] = v.y;
            As[kq + 2][row] = v.z; As[kq + 3][row] = v.w;
        }
#pragma unroll
        for (int it = 0; it < 2; it++) {
            int lin = tid * 2 + it;
            int kl = lin >> 4;
            int n4 = (lin & 15) << 2;
            float4 v = *(const float4*)(g_W0xT + (kc + kl) * SW0X + n0 + n4);
            *(float4*)&Bs[kl][n4] = v;
        }
        __syncthreads();
#pragma unroll
        for (int kl = 0; kl < 32; kl++) {
            float4 a = *(float4*)&As[kl][ty << 2];
            float4 b = *(float4*)&Bs[kl][tx << 2];
            acc[0][0] = fmaf(a.x, b.x, acc[0][0]); acc[0][1] = fmaf(a.x, b.y, acc[0][1]);
            acc[0][2] = fmaf(a.x, b.z, acc[0][2]); acc[0][3] = fmaf(a.x, b.w, acc[0][3]);
            acc[1][0] = fmaf(a.y, b.x, acc[1][0]); acc[1][1] = fmaf(a.y, b.y, acc[1][1]);
            acc[1][2] = fmaf(a.y, b.z, acc[1][2]); acc[1][3] = fmaf(a.y, b.w, acc[1][3]);
            acc[2][0] = fmaf(a.z, b.x, acc[2][0]); acc[2][1] = fmaf(a.z, b.y, acc[2][1]);
            acc[2][2] = fmaf(a.z, b.z, acc[2][2]); acc[2][3] = fmaf(a.z, b.w, acc[2][3]);
            acc[3][0] = fmaf(a.w, b.x, acc[3][0]); acc[3][1] = fmaf(a.w, b.y, acc[3][1]);
            acc[3][2] = fmaf(a.w, b.z, acc[3][2]); acc[3][3] = fmaf(a.w, b.w, acc[3][3]);
        }
        __syncthreads();
    }
#pragma unroll
    for (int i = 0; i < 4; i++) {
        int m = m0 + (ty << 2) + i;
#pragma unroll
        for (int j = 0; j < 4; j++) {
            int n = n0 + (tx << 2) + j;
            if (n < SU0) g_U0[(size_t)m * SU0 + n] = acc[i][j] + g_b0c[n];
        }
    }
}

// ---------------- scan: 64 blocks x 512 threads, 2 batch rows / block ----------------
#define OFF_W0C 0
#define OFF_W2C 50160
#define OFF_B1C 51408
#define OFF_B2C 51712
#define OFF_D1  51728
#define OFF_D2  52236
#define OFF_P0  52444
#define OFF_P1  54268
#define OFF_P2  56092
#define SMEM_FLOATS 56236
#define SMEM_BYTES (SMEM_FLOATS * 4)

__global__ void __launch_bounds__(512, 1) scan_kernel(float* __restrict__ out) {
    extern __shared__ float sm[];
    float*  W0c = sm + OFF_W0C;             // [110][456]
    float*  W2c = sm + OFF_W2C;             // [104][12]
    float*  b1c = sm + OFF_B1C;             // [304]
    float*  b2c = sm + OFF_B2C;             // [16]
    float2* d1s = (float2*)(sm + OFF_D1);   // [253] = [h0 | h1], rows packed
    float2* d2s = (float2*)(sm + OFF_D2);   // [104] = [h1 | h2]
    float4* p0  = (float4*)(sm + OFF_P0);   // [2][228] partials L0
    float4* p1  = (float4*)(sm + OFF_P1);   // [3][152] partials L1
    float2* p2  = (float2*)(sm + OFF_P2);   // [8][9]   partials L2

    int tid = threadIdx.x;
    int rowA = blockIdx.x * 2, rowB = rowA + 1;

    for (int i = tid; i < KC0 * SU0; i += 512) W0c[i] = g_W0hT[i];
    for (int i = tid; i < D2 * G2P; i += 512) W2c[i] = g_W2T[i];
    if (tid < G1P) b1c[tid] = g_b1c[tid];
    if (tid < 16) b2c[tid] = g_b2c[tid];
    for (int i = tid; i < D1; i += 512) d1s[i] = make_float2(0.f, 0.f);
    for (int i = tid; i < D2; i += 512) d2s[i] = make_float2(0.f, 0.f);
    __syncthreads();

    const float* U0a = g_U0 + (size_t)rowA * TT * SU0;
    const float* U0b = g_U0 + (size_t)rowB * TT * SU0;

    int cp0 = tid % 228, ks0 = tid / 228;   // layer0: 228 col-pairs x 2 k-chunks
    int cp1 = tid % 152, ks1 = tid / 152;   // layer1: 152 col-pairs x 3 k-chunks
    int j2  = tid % 9,   ks2 = tid / 9;     // layer2: 9 cols x 8 k-chunks

    for (int t = 0; t < TT; t++) {
        // ---- A: layer-0 gate partials ----
        if (tid < 456) {
            int c0 = cp0 * 2;
            float4 acc;
            if (ks0 == 0) {
                const float* ua = U0a + (size_t)t * SU0;
                const float* ub = U0b + (size_t)t * SU0;
                float2 va = *(const float2*)(ua + c0);
                float2 vb = *(const float2*)(ub + c0);
                acc = make_float4(va.x, vb.x, va.y, vb.y);
                for (int k = 0; k < 76; k++) {
                    float2 w = *(const float2*)&W0c[k * SU0 + c0];
                    float2 d = d1s[k];
                    acc.x = fmaf(w.x, d.x, acc.x); acc.y = fmaf(w.x, d.y, acc.y);
                    acc.z = fmaf(w.y, d.x, acc.z); acc.w = fmaf(w.y, d.y, acc.w);
                }
            } else {
                acc = make_float4(0.f, 0.f, 0.f, 0.f);
                for (int k = 76; k < KC0; k++) {
                    float2 w = *(const float2*)&W0c[k * SU0 + c0];
                    float2 d = d1s[k];
                    acc.x = fmaf(w.x, d.x, acc.x); acc.y = fmaf(w.x, d.y, acc.y);
                    acc.z = fmaf(w.y, d.x, acc.z); acc.w = fmaf(w.y, d.y, acc.w);
                }
                for (int k = KC0; k < H0; k++) {
                    float2 w = *(const float2*)&g_W0hT[k * SU0 + c0];
                    float2 d = d1s[k];
                    acc.x = fmaf(w.x, d.x, acc.x); acc.y = fmaf(w.x, d.y, acc.y);
                    acc.z = fmaf(w.y, d.x, acc.z); acc.w = fmaf(w.y, d.y, acc.w);
                }
            }
            p0[ks0 * 228 + cp0] = acc;
        }
        __syncthreads();
        // ---- B: h0 update ----
        if (tid < H0) {
            int j = tid;
            float ga[3][2];
#pragma unroll
            for (int g = 0; g < 3; g++) {
                int c = g * H0 + j;
                int cp = c >> 1, lane = (c & 1) << 1;
                const float* q0 = (const float*)&p0[cp];
                const float* q1 = (const float*)&p0[228 + cp];
                ga[g][0] = q0[lane] + q1[lane];
                ga[g][1] = q0[lane + 1] + q1[lane + 1];
            }
            float2 h;
            { float s = sig_f(ga[2][0]); h.x = tanh_f(ga[0][0]) * (1.f - s) + s * tanh_f(ga[1][0]); }
            { float s = sig_f(ga[2][1]); h.y = tanh_f(ga[0][1]) * (1.f - s) + s * tanh_f(ga[1][1]); }
            d1s[j] = h;
        }
        __syncthreads();
        // ---- C: layer-1 gate partials ----
        if (tid < 456) {
            int c0 = cp1 * 2;
            int k0 = ks1 * 85, k1 = k0 + 85; if (k1 > D1) k1 = D1;
            float4 acc = (ks1 == 0) ? make_float4(b1c[c0], b1c[c0], b1c[c0 + 1], b1c[c0 + 1])
                                    : make_float4(0.f, 0.f, 0.f, 0.f);
            for (int k = k0; k < k1; k++) {
                float2 w = *(const float2*)&g_W1T[k * G1P + c0];
                float2 d = d1s[k];
                acc.x = fmaf(w.x, d.x, acc.x); acc.y = fmaf(w.x, d.y, acc.y);
                acc.z = fmaf(w.y, d.x, acc.z); acc.w = fmaf(w.y, d.y, acc.w);
            }
            p1[ks1 * 152 + cp1] = acc;
        }
        __syncthreads();
        // ---- D: h1 update ----
        if (tid < H1) {
            int j = tid;
            float ga[3][2];
#pragma unroll
            for (int g = 0; g < 3; g++) {
                int c = g * H1 + j;
                int cp = c >> 1, lane = (c & 1) << 1;
                const float* q0 = (const float*)&p1[cp];
                const float* q1 = (const float*)&p1[152 + cp];
                const float* q2 = (const float*)&p1[304 + cp];
                ga[g][0] = q0[lane] + q1[lane] + q2[lane];
                ga[g][1] = q0[lane + 1] + q1[lane + 1] + q2[lane + 1];
            }
            float2 h;
            { float s = sig_f(ga[2][0]); h.x = tanh_f(ga[0][0]) * (1.f - s) + s * tanh_f(ga[1][0]); }
            { float s = sig_f(ga[2][1]); h.y = tanh_f(ga[0][1]) * (1.f - s) + s * tanh_f(ga[1][1]); }
            d1s[H0 + j] = h;
            d2s[j] = h;
        }
        __syncthreads();
        // ---- E: layer-2 gate partials ----
        if (tid < 72) {
            int k0 = ks2 * 13, k1 = k0 + 13;
            float2 acc = (ks2 == 0) ? make_float2(b2c[j2], b2c[j2]) : make_float2(0.f, 0.f);
            for (int k = k0; k < k1; k++) {
                float w = W2c[k * G2P + j2];
                float2 d = d2s[k];
                acc.x = fmaf(w, d.x, acc.x); acc.y = fmaf(w, d.y, acc.y);
            }
            p2[ks2 * 9 + j2] = acc;
        }
        __syncthreads();
        // ---- F: h2 update + control outputs ----
        if (tid < 3) {
            int j = tid;
            float2 f1 = make_float2(0.f, 0.f), f2 = make_float2(0.f, 0.f), tg = make_float2(0.f, 0.f);
#pragma unroll
            for (int s = 0; s < 8; s++) {
                float2 a = p2[s * 9 + j];     f1.x += a.x; f1.y += a.y;
                float2 b = p2[s * 9 + 3 + j]; f2.x += b.x; f2.y += b.y;
                float2 c = p2[s * 9 + 6 + j]; tg.x += c.x; tg.y += c.y;
            }
            float2 h;
            { float s = sig_f(tg.x); h.x = tanh_f(f1.x) * (1.f - s) + s * tanh_f(f2.x); }
            { float s = sig_f(tg.y); h.y = tanh_f(f1.y) * (1.f - s) + s * tanh_f(f2.y); }
            d2s[H1 + j] = h;
            float ca = (j == 0) ? tanh_f(h.x) : sig_f(h.x);
            float cb = (j == 0) ? tanh_f(h.y) : sig_f(h.y);
            out[((size_t)rowA * TT + t) * 3 + j] = ca;
            out[((size_t)rowB * TT + t) * 3 + j] = cb;
        }
        __syncthreads();
    }

    // final hidden state hx = [h0 | h1 | h2], [B][256], after controls
    float* hx = out + (size_t)BATCH * TT * 3;
    if (tid < D1) {
        float2 h = d1s[tid];
        hx[rowA * 256 + tid] = h.x;
        hx[rowB * 256 + tid] = h.y;
    } else if (tid < 256) {
        int j = tid - D1;
        float2 h = d2s[H1 + j];
        hx[rowA * 256 + D1 + j] = h.x;
        hx[rowB * 256 + D1 + j] = h.y;
    }
}

// ---------------- launch ----------------
extern "C" void kernel_launch(void* const* d_in, const int* in_sizes, int n_in,
                              void* d_out, int out_size) {
    const float* feat = (const float*)d_in[0];
    const float* cmd  = (const float*)d_in[1];
    const float* l0W  = (const float*)d_in[2];
    const float* l0b  = (const float*)d_in[3];
    const float* l1W  = (const float*)d_in[4];
    const float* l1b  = (const float*)d_in[5];
    const float* l2W  = (const float*)d_in[6];
    const float* l2b  = (const float*)d_in[7];
    const float* m0   = (const float*)d_in[8];
    const float* m1   = (const float*)d_in[9];
    const float* m2   = (const float*)d_in[10];
    float* out = (float*)d_out;

    prep_kernel<<<256, 256>>>(l0W, l0b, l1W, l1b, l2W, l2b, m0, m1, m2);

    dim3 gg(8, 1024);
    gemm_u0<<<gg, 256>>>(feat, cmd);

    cudaFuncSetAttribute(scan_kernel, cudaFuncAttributeMaxDynamicSharedMemorySize, SMEM_BYTES);
    scan_kernel<<<BATCH / 2, 512, SMEM_BYTES>>>(out);
}